// round 15
// baseline (speedup 1.0000x reference)
#include <cuda_runtime.h>
#include <cuda_fp16.h>
#include <cstdint>

#define BATCH  4
#define SEQ    2048
#define DMODEL 768
#define NHEAD  12
#define HSZ    64
#define MROWS  (BATCH*SEQ)

// Scratch (alloc-free rule).
__device__ __half g_hW[4][DMODEL*DMODEL];    // converted W_Q/W_K/W_V/W_O
__device__ __half g_Q  [MROWS*DMODEL];
__device__ __half g_K  [MROWS*DMODEL];
__device__ __half g_V  [MROWS*DMODEL];
__device__ __half g_Ctx[MROWS*DMODEL];

__device__ __forceinline__ uint32_t pkh2(float lo, float hi) {
    uint32_t d;
    asm("cvt.rn.f16x2.f32 %0, %1, %2;" : "=r"(d) : "f"(hi), "f"(lo));
    return d;
}
__device__ __forceinline__ uint32_t h2ex2(uint32_t x) {
    uint32_t d; asm("ex2.approx.f16x2 %0, %1;" : "=r"(d) : "r"(x)); return d;
}
__device__ __forceinline__ uint32_t smem_u32(const void* p) {
    uint32_t a;
    asm("{ .reg .u64 t; cvta.to.shared.u64 t, %1; cvt.u32.u64 %0, t; }"
        : "=r"(a) : "l"(p));
    return a;
}

#define MMA_F16(d, a, b0v, b1v)                                                \
    asm volatile("mma.sync.aligned.m16n8k16.row.col.f32.f16.f16.f32 "          \
        "{%0,%1,%2,%3}, {%4,%5,%6,%7}, {%8,%9}, {%0,%1,%2,%3};"                \
        : "+f"((d)[0]), "+f"((d)[1]), "+f"((d)[2]), "+f"((d)[3])               \
        : "r"((a)[0]), "r"((a)[1]), "r"((a)[2]), "r"((a)[3]),                  \
          "r"(b0v), "r"(b1v))

#define LDSM4(r, addr)                                                         \
    asm volatile("ldmatrix.sync.aligned.m8n8.x4.shared.b16 {%0,%1,%2,%3}, [%4];" \
        : "=r"((r)[0]), "=r"((r)[1]), "=r"((r)[2]), "=r"((r)[3]) : "r"(addr))
#define LDSM4T(r, addr)                                                        \
    asm volatile("ldmatrix.sync.aligned.m8n8.x4.trans.shared.b16 {%0,%1,%2,%3}, [%4];" \
        : "=r"((r)[0]), "=r"((r)[1]), "=r"((r)[2]), "=r"((r)[3]) : "r"(addr))

#define CP16(dst, src)                                                         \
    asm volatile("cp.async.cg.shared.global [%0], [%1], 16;" :: "r"(dst), "l"(src))
#define CP_COMMIT() asm volatile("cp.async.commit_group;" ::: "memory")
#define CP_WAIT(n)  asm volatile("cp.async.wait_group %0;" :: "n"(n) : "memory")

// ---------------------------------------------------------------------------
// fp32 -> fp16 conversion: weights only now (X converts inside gemm_qkv)
// ---------------------------------------------------------------------------
struct Cvt4 { const float* s[4]; __half* d[4]; };

__global__ __launch_bounds__(256)
void convert_k(Cvt4 c) {
    const int y = blockIdx.y;
    const float4* s = (const float4*)c.s[y];
    uint4* d = (uint4*)c.d[y];
    const int n8 = DMODEL * DMODEL / 8;
    for (int i = blockIdx.x * 256 + threadIdx.x; i < n8; i += gridDim.x * 256) {
        float4 v0 = s[2 * i], v1 = s[2 * i + 1];
        d[i] = make_uint4(pkh2(v0.x, v0.y), pkh2(v0.z, v0.w),
                          pkh2(v1.x, v1.y), pkh2(v1.z, v1.w));
    }
}

// ---------------------------------------------------------------------------
// GEMM common config: CTA 128x128, 8 warps 2(M)x4(N), warp 64x32,
// k-chunk 64 halves, 3-stage pipeline, GS=36 (32 data + 4 pad words).
// ---------------------------------------------------------------------------
#define GS   36
#define GBUF (128 * GS)
#define GEMM_SMEM (3 * 2 * GBUF * 4)    // 110592 B

__device__ __forceinline__ void stY(float* Y, size_t off, float v0, float v1) {
    *(float2*)(Y + off) = make_float2(v0, v1);
}
__device__ __forceinline__ void stY(__half* Y, size_t off, float v0, float v1) {
    *(uint32_t*)(Y + off) = pkh2(v0, v1);
}

// compute epilogue shared by both bodies
#define GEMM_EPILOGUE()                                                        \
    _Pragma("unroll")                                                          \
    for (int mt = 0; mt < 4; mt++) {                                           \
        const int row = m0 + wm + mt * 16 + g;                                 \
        _Pragma("unroll")                                                      \
        for (int nt = 0; nt < 4; nt++) {                                       \
            const int col = n0 + wn + nt * 8 + 2 * tg;                         \
            const float b0v = bias[col], b1v = bias[col + 1];                  \
            stY(Y, (size_t)row * DMODEL + col,                                 \
                (acc[mt][nt][0] + b0v) * osc, (acc[mt][nt][1] + b1v) * osc);   \
            stY(Y, (size_t)(row + 8) * DMODEL + col,                           \
                (acc[mt][nt][2] + b0v) * osc, (acc[mt][nt][3] + b1v) * osc);   \
        }                                                                      \
    }

#define GEMM_COMPUTE(kt)                                                       \
    do {                                                                       \
        const uint32_t sb2 = sbase + ((kt) % 3) * 2 * GBUF * 4;                \
        const uint32_t ao = sb2 + aF;                                          \
        const uint32_t bo = sb2 + GBUF * 4 + bF;                               \
        _Pragma("unroll")                                                      \
        for (int k16 = 0; k16 < 4; k16++) {                                    \
            uint32_t a4[4][4], b4[2][4];                                       \
            _Pragma("unroll")                                                  \
            for (int mt = 0; mt < 4; mt++)                                     \
                LDSM4(a4[mt], ao + (uint32_t)((mt * 16 * GS + k16 * 8) << 2)); \
            _Pragma("unroll")                                                  \
            for (int np = 0; np < 2; np++)                                     \
                LDSM4(b4[np], bo + (uint32_t)((np * 16 * GS + k16 * 8) << 2)); \
            _Pragma("unroll")                                                  \
            for (int mt = 0; mt < 4; mt++)                                     \
                _Pragma("unroll")                                              \
                for (int nt = 0; nt < 4; nt++)                                 \
                    MMA_F16(acc[mt][nt], a4[mt],                               \
                            b4[nt >> 1][(nt & 1) * 2],                         \
                            b4[nt >> 1][(nt & 1) * 2 + 1]);                    \
        }                                                                      \
    } while (0)

// ---------------------------------------------------------------------------
// Body A: fp32 activations (QKV projections). A-tile: LDG fp32 -> cvt regs
// (one iter ahead) -> STS; B-tile (weights): cp.async (groups = B only).
// ---------------------------------------------------------------------------
__device__ __forceinline__ void gemm_body_f32a(
    const float* __restrict__ X, const __half* __restrict__ W,
    const float* __restrict__ bias, __half* __restrict__ Y, int m0, int n0,
    float osc)
{
    extern __shared__ uint32_t dsm[];
    const uint32_t sbase = smem_u32(dsm);
    const int tid = threadIdx.x, lane = tid & 31, wid = tid >> 5;
    const int g = lane >> 2, tg = lane & 3;
    const int wm = (wid & 1) * 64, wn = (wid >> 1) * 32;

    const float*  Xb = X + (size_t)m0 * DMODEL;
    const __half* Wb = W + (size_t)n0 * DMODEL;
    const int r0 = tid >> 3, c0 = tid & 7;   // row 0..31, 16B-halfchunk 0..7

    float acc[4][4][4] = {};
    uint4 xr[4];   // A[kt+1] held as packed halves

#define GA_LD(kt) do {                                                         \
        _Pragma("unroll")                                                      \
        for (int j = 0; j < 4; j++) {                                          \
            const int r = r0 + j * 32;                                         \
            const float* p = Xb + (size_t)r * DMODEL + (kt) * 64 + c0 * 8;     \
            float4 v0 = *(const float4*)p;                                     \
            float4 v1 = *(const float4*)(p + 4);                               \
            xr[j] = make_uint4(pkh2(v0.x, v0.y), pkh2(v0.z, v0.w),             \
                               pkh2(v1.x, v1.y), pkh2(v1.z, v1.w));            \
        } } while (0)

#define GA_ST(kt) do {                                                         \
        uint32_t* ab = dsm + ((kt) % 3) * 2 * GBUF;                            \
        _Pragma("unroll")                                                      \
        for (int j = 0; j < 4; j++) {                                          \
            const int r = r0 + j * 32;                                         \
            *(uint4*)&ab[r * GS + c0 * 4] = xr[j];                             \
        } } while (0)

#define GB_ISSUE(kt, s) do {                                                   \
        uint32_t bb = sbase + (s) * 2 * GBUF * 4 + GBUF * 4;                   \
        _Pragma("unroll")                                                      \
        for (int j = 0; j < 4; j++) {                                          \
            const int r = r0 + j * 32;                                         \
            const uint32_t off = (uint32_t)(r * GS + c0 * 4) << 2;             \
            CP16(bb + off, Wb + (size_t)r * DMODEL + (kt) * 64 + c0 * 8);      \
        } } while (0)

    GA_LD(0); GA_ST(0); GA_LD(1);
    GB_ISSUE(0, 0); CP_COMMIT();
    GB_ISSUE(1, 1); CP_COMMIT();

    const uint32_t aF = (uint32_t)((wm + (lane & 15)) * GS + (lane >> 4) * 4) << 2;
    const uint32_t bF = (uint32_t)((wn + (lane >> 4) * 8 + (lane & 7)) * GS
                                   + ((lane >> 3) & 1) * 4) << 2;

    const int NK = DMODEL / 64;   // 12
    for (int kt = 0; kt < NK; kt++) {
        CP_WAIT(1);
        __syncthreads();
        if (kt + 1 < NK) GA_ST(kt + 1);        // slot (kt+1)%3: free since kt-2
        if (kt + 2 < NK) { GA_LD(kt + 2); GB_ISSUE(kt + 2, (kt + 2) % 3); }
        CP_COMMIT();
        GEMM_COMPUTE(kt);
    }
#undef GA_LD
#undef GA_ST
#undef GB_ISSUE

    GEMM_EPILOGUE();
}

// ---------------------------------------------------------------------------
// Body B (R13-proven): fp16 A and B, both via cp.async. Used by gemm_out.
// ---------------------------------------------------------------------------
__device__ __forceinline__ void gemm_body_f16a(
    const __half* __restrict__ X, const __half* __restrict__ W,
    const float* __restrict__ bias, float* __restrict__ Y, int m0, int n0,
    float osc)
{
    extern __shared__ uint32_t dsm[];
    const uint32_t sbase = smem_u32(dsm);
    const int tid = threadIdx.x, lane = tid & 31, wid = tid >> 5;
    const int g = lane >> 2, tg = lane & 3;
    const int wm = (wid & 1) * 64, wn = (wid >> 1) * 32;

    const __half* Xb = X + (size_t)m0 * DMODEL;
    const __half* Wb = W + (size_t)n0 * DMODEL;
    const int r0 = tid >> 3, c0 = tid & 7;

    float acc[4][4][4] = {};

#define G_ISSUE(kt, s) do {                                                    \
        uint32_t ab = sbase + (s) * 2 * GBUF * 4;                              \
        uint32_t bb = ab + GBUF * 4;                                           \
        _Pragma("unroll")                                                      \
        for (int j = 0; j < 4; j++) {                                          \
            const int r = r0 + j * 32;                                         \
            const uint32_t off = (uint32_t)(r * GS + c0 * 4) << 2;             \
            CP16(ab + off, Xb + (size_t)r * DMODEL + (kt) * 64 + c0 * 8);      \
            CP16(bb + off, Wb + (size_t)r * DMODEL + (kt) * 64 + c0 * 8);      \
        } } while (0)

    G_ISSUE(0, 0); CP_COMMIT();
    G_ISSUE(1, 1); CP_COMMIT();

    const uint32_t aF = (uint32_t)((wm + (lane & 15)) * GS + (lane >> 4) * 4) << 2;
    const uint32_t bF = (uint32_t)((wn + (lane >> 4) * 8 + (lane & 7)) * GS
                                   + ((lane >> 3) & 1) * 4) << 2;

    const int NK = DMODEL / 64;   // 12
    for (int kt = 0; kt < NK; kt++) {
        CP_WAIT(1);
        __syncthreads();
        if (kt + 2 < NK) { G_ISSUE(kt + 2, (kt + 2) % 3); }
        CP_COMMIT();
        GEMM_COMPUTE(kt);
    }
#undef G_ISSUE

    GEMM_EPILOGUE();
}

#define QS2 (0.125f * 1.44269504f)   // 1/sqrt(64) * log2(e)

__global__ __launch_bounds__(256, 2)
void gemm_qkv(const float* __restrict__ X0, const float* __restrict__ X1,
              const float* __restrict__ X2,
              const __half* __restrict__ W0, const float* __restrict__ b0p,
              const __half* __restrict__ W1, const float* __restrict__ b1p,
              const __half* __restrict__ W2, const float* __restrict__ b2p,
              __half* __restrict__ Q, __half* __restrict__ K, __half* __restrict__ V)
{
    const int m0 = blockIdx.y * 128, n0 = blockIdx.x * 128;
    if (blockIdx.z == 0)      gemm_body_f32a(X0, W0, b0p, Q, m0, n0, QS2);
    else if (blockIdx.z == 1) gemm_body_f32a(X1, W1, b1p, K, m0, n0, 1.f);
    else                      gemm_body_f32a(X2, W2, b2p, V, m0, n0, 1.f);
}

__global__ __launch_bounds__(256, 2)
void gemm_out(const __half* __restrict__ X, const __half* __restrict__ W,
              const float* __restrict__ bias, float* __restrict__ Y)
{
    gemm_body_f16a(X, W, bias, Y, blockIdx.y * 128, blockIdx.x * 128, 1.f);
}

// ---------------------------------------------------------------------------
// fp16 flash attention (R13-proven, unchanged). Unnormalized softmax.
// CTA = 128 q rows, 8 warps x 16. 128-row K-tiles, 3-stage cp.async.
// ---------------------------------------------------------------------------
#define ASH  36
#define ABUF (128 * ASH)
#define ATTN_SMEM (3 * 2 * ABUF * 4)     // 110592 B
#define ONES_H2 0x3C003C00u

__global__ __launch_bounds__(256, 2)
void attn_mma(const __half* __restrict__ Q, const __half* __restrict__ K,
              const __half* __restrict__ V, __half* __restrict__ O)
{
    extern __shared__ uint32_t dsm[];
    const uint32_t sbase = smem_u32(dsm);

    const int tid = threadIdx.x, wid = tid >> 5, lane = tid & 31;
    const int g = lane >> 2, tg = lane & 3;
    const int bh = blockIdx.y, b = bh / NHEAD, h = bh % NHEAD;
    const int q0 = ((int)gridDim.x - 1 - (int)blockIdx.x) * 128;  // heavy first
    const int wslab = wid * 16;

    const __half* Qg = Q + (size_t)b * SEQ * DMODEL + h * HSZ;
    const __half* Kg = K + (size_t)b * SEQ * DMODEL + h * HSZ;
    const __half* Vg = V + (size_t)b * SEQ * DMODEL + h * HSZ;

    const int row0 = q0 + wslab + g;
    const int row1 = row0 + 8;

    uint32_t qh[4][4];
    {
        const __half* Qr0 = Qg + (size_t)row0 * DMODEL;
        const __half* Qr1 = Qg + (size_t)row1 * DMODEL;
#pragma unroll
        for (int j = 0; j < 4; j++) {
            const int c = j * 16 + 2 * tg;
            qh[j][0] = *(const uint32_t*)(Qr0 + c);
            qh[j][1] = *(const uint32_t*)(Qr1 + c);
            qh[j][2] = *(const uint32_t*)(Qr0 + c + 8);
            qh[j][3] = *(const uint32_t*)(Qr1 + c + 8);
        }
    }

    const int ar0 = tid >> 3, ac0 = tid & 7;

#define A_ISSUE(kt, s) do {                                                    \
        uint32_t kb = sbase + (s) * 2 * ABUF * 4;                              \
        uint32_t vb = kb + ABUF * 4;                                           \
        _Pragma("unroll")                                                      \
        for (int j = 0; j < 4; j++) {                                          \
            const int r = ar0 + j * 32;                                        \
            const uint32_t off = (uint32_t)(r * ASH + ac0 * 4) << 2;           \
            CP16(kb + off, Kg + (size_t)((kt) + r) * DMODEL + ac0 * 8);        \
            CP16(vb + off, Vg + (size_t)((kt) + r) * DMODEL + ac0 * 8);        \
        } } while (0)

    const uint32_t kF = (uint32_t)(((lane >> 4) * 8 + (lane & 7)) * ASH
                                   + ((lane >> 3) & 1) * 4) << 2;
    const uint32_t vF = (uint32_t)((((lane >> 3) & 1) * 8 + (lane & 7)) * ASH
                                   + (lane >> 4) * 4) << 2;

    float o[8][4] = {};
    float ol[4] = {};

    const int nt128 = q0 / 128 + 1;
    A_ISSUE(0, 0); CP_COMMIT();
    if (nt128 > 1) A_ISSUE(128, 1);
    CP_COMMIT();

    for (int t = 0; t < nt128; t++) {
        const int kt = t * 128;
        CP_WAIT(1);
        __syncthreads();
        if (t + 2 < nt128) A_ISSUE((t + 2) * 128, (t + 2) % 3);
        CP_COMMIT();

        const uint32_t sb2 = sbase + (t % 3) * 2 * ABUF * 4;

#pragma unroll
        for (int hh = 0; hh < 2; hh++) {
            const int kb0 = kt + hh * 64;
            if (kb0 >= q0 + wslab + 16) break;

            const uint32_t hoff = (uint32_t)(hh * 64 * ASH) << 2;
            const uint32_t ko = sb2 + hoff + kF;
            const uint32_t vo = sb2 + ABUF * 4 + hoff + vF;

            float s[8][4] = {};
#pragma unroll
            for (int j = 0; j < 4; j++) {
                uint32_t kb4[4][4];
#pragma unroll
                for (int np = 0; np < 4; np++)
                    LDSM4(kb4[np], ko + (uint32_t)((np * 16 * ASH + j * 8) << 2));
#pragma unroll
                for (int nt = 0; nt < 8; nt++)
                    MMA_F16(s[nt], qh[j],
                            kb4[nt >> 1][(nt & 1) * 2], kb4[nt >> 1][(nt & 1) * 2 + 1]);
            }

            if (kb0 + 64 > q0 + wslab) {
#pragma unroll
                for (int nt = 0; nt < 8; nt++) {
                    const int cl = kb0 + nt * 8 + 2 * tg;
                    if (cl     > row0) s[nt][0] = -1e30f;
                    if (cl + 1 > row0) s[nt][1] = -1e30f;
                    if (cl     > row1) s[nt][2] = -1e30f;
                    if (cl + 1 > row1) s[nt][3] = -1e30f;
                }
            }

#pragma unroll
            for (int j = 0; j < 4; j++) {
                uint32_t pa[4];
                pa[0] = h2ex2(pkh2(s[2*j  ][0], s[2*j  ][1]));
                pa[1] = h2ex2(pkh2(s[2*j  ][2], s[2*j  ][3]));
                pa[2] = h2ex2(pkh2(s[2*j+1][0], s[2*j+1][1]));
                pa[3] = h2ex2(pkh2(s[2*j+1][2], s[2*j+1][3]));
                MMA_F16(ol, pa, ONES_H2, ONES_H2);
#pragma unroll
                for (int dtp = 0; dtp < 4; dtp++) {
                    uint32_t vb4[4];
                    LDSM4T(vb4, vo + (uint32_t)((j * 16 * ASH + dtp * 8) << 2));
                    MMA_F16(o[2*dtp    ], pa, vb4[0], vb4[1]);
                    MMA_F16(o[2*dtp + 1], pa, vb4[2], vb4[3]);
                }
            }
        }
    }
#undef A_ISSUE

    const float i0 = 1.f / ol[0], i1 = 1.f / ol[2];
    __half* Op = O + (size_t)b * SEQ * DMODEL + h * HSZ;
#pragma unroll
    for (int dt = 0; dt < 8; dt++) {
        const int col = dt * 8 + 2 * tg;
        *(uint32_t*)(Op + (size_t)row0 * DMODEL + col) = pkh2(o[dt][0] * i0, o[dt][1] * i0);
        *(uint32_t*)(Op + (size_t)row1 * DMODEL + col) = pkh2(o[dt][2] * i1, o[dt][3] * i1);
    }
}

// ---------------------------------------------------------------------------
extern "C" void kernel_launch(void* const* d_in, const int* in_sizes, int n_in,
                              void* d_out, int out_size)
{
    const float* queries = (const float*)d_in[0];
    const float* keys    = (const float*)d_in[1];
    const float* values  = (const float*)d_in[2];
    const float* W_Q = (const float*)d_in[3];
    const float* b_Q = (const float*)d_in[4];
    const float* W_K = (const float*)d_in[5];
    const float* b_K = (const float*)d_in[6];
    const float* W_V = (const float*)d_in[7];
    const float* b_V = (const float*)d_in[8];
    const float* W_O = (const float*)d_in[9];
    const float* b_O = (const float*)d_in[10];
    float* out = (float*)d_out;

    __half *hW, *pQ, *pK, *pV, *pC;
    cudaGetSymbolAddress((void**)&hW, g_hW);
    cudaGetSymbolAddress((void**)&pQ, g_Q);
    cudaGetSymbolAddress((void**)&pK, g_K);
    cudaGetSymbolAddress((void**)&pV, g_V);
    cudaGetSymbolAddress((void**)&pC, g_Ctx);

    __half* hWQ = hW;
    __half* hWK = hW + (size_t)DMODEL * DMODEL;
    __half* hWV = hW + 2 * (size_t)DMODEL * DMODEL;
    __half* hWO = hW + 3 * (size_t)DMODEL * DMODEL;

    Cvt4 c;
    c.s[0] = W_Q; c.d[0] = hWQ;
    c.s[1] = W_K; c.d[1] = hWK;
    c.s[2] = W_V; c.d[2] = hWV;
    c.s[3] = W_O; c.d[3] = hWO;
    dim3 gc(288, 4);                         // 768*768/8/256 = 288
    convert_k<<<gc, 256>>>(c);

    cudaFuncSetAttribute(gemm_qkv, cudaFuncAttributeMaxDynamicSharedMemorySize, GEMM_SMEM);
    cudaFuncSetAttribute(gemm_out, cudaFuncAttributeMaxDynamicSharedMemorySize, GEMM_SMEM);
    cudaFuncSetAttribute(attn_mma, cudaFuncAttributeMaxDynamicSharedMemorySize, ATTN_SMEM);

    dim3 g3(DMODEL / 128, MROWS / 128, 3);   // (6, 64, 3)
    gemm_qkv<<<g3, 256, GEMM_SMEM>>>(queries, keys, values,
                                     hWQ, b_Q, hWK, b_K, hWV, b_V, pQ, pK, pV);

    dim3 ga(SEQ / 128, BATCH * NHEAD);       // (16, 48)
    attn_mma<<<ga, 256, ATTN_SMEM>>>(pQ, pK, pV, pC);

    dim3 gg(DMODEL / 128, MROWS / 128);      // (6, 64)
    gemm_out<<<gg, 256, GEMM_SMEM>>>(pC, hWO, b_O, out);
}

// round 16
// speedup vs baseline: 1.0782x; 1.0782x over previous
#include <cuda_runtime.h>
#include <cuda_fp16.h>
#include <cstdint>

#define BATCH  4
#define SEQ    2048
#define DMODEL 768
#define NHEAD  12
#define HSZ    64
#define MROWS  (BATCH*SEQ)

// Scratch (alloc-free rule). Half precision everywhere.
__device__ __half g_hX[3][MROWS*DMODEL];     // converted queries/keys/values
__device__ __half g_hW[4][DMODEL*DMODEL];    // converted W_Q/W_K/W_V/W_O
__device__ __half g_Q  [MROWS*DMODEL];
__device__ __half g_K  [MROWS*DMODEL];
__device__ __half g_V  [MROWS*DMODEL];
__device__ __half g_Ctx[MROWS*DMODEL];

__device__ __forceinline__ uint32_t pkh2(float lo, float hi) {
    uint32_t d;
    asm("cvt.rn.f16x2.f32 %0, %1, %2;" : "=r"(d) : "f"(hi), "f"(lo));
    return d;
}
__device__ __forceinline__ uint32_t h2ex2(uint32_t x) {
    uint32_t d; asm("ex2.approx.f16x2 %0, %1;" : "=r"(d) : "r"(x)); return d;
}
__device__ __forceinline__ uint32_t smem_u32(const void* p) {
    uint32_t a;
    asm("{ .reg .u64 t; cvta.to.shared.u64 t, %1; cvt.u32.u64 %0, t; }"
        : "=r"(a) : "l"(p));
    return a;
}

// fp32-accumulator MMA (GEMMs, PV, ones)
#define MMA_F16(d, a, b0v, b1v)                                                \
    asm volatile("mma.sync.aligned.m16n8k16.row.col.f32.f16.f16.f32 "          \
        "{%0,%1,%2,%3}, {%4,%5,%6,%7}, {%8,%9}, {%0,%1,%2,%3};"                \
        : "+f"((d)[0]), "+f"((d)[1]), "+f"((d)[2]), "+f"((d)[3])               \
        : "r"((a)[0]), "r"((a)[1]), "r"((a)[2]), "r"((a)[3]),                  \
          "r"(b0v), "r"(b1v))

// fp16-accumulator MMA (attention S) — 2x tensor rate, accum layout == A-frag
#define MMA_F16H(c01, c23, a, b0v, b1v)                                        \
    asm volatile("mma.sync.aligned.m16n8k16.row.col.f16.f16.f16.f16 "          \
        "{%0,%1}, {%2,%3,%4,%5}, {%6,%7}, {%0,%1};"                            \
        : "+r"(c01), "+r"(c23)                                                 \
        : "r"((a)[0]), "r"((a)[1]), "r"((a)[2]), "r"((a)[3]),                  \
          "r"(b0v), "r"(b1v))

#define LDSM4(r, addr)                                                         \
    asm volatile("ldmatrix.sync.aligned.m8n8.x4.shared.b16 {%0,%1,%2,%3}, [%4];" \
        : "=r"((r)[0]), "=r"((r)[1]), "=r"((r)[2]), "=r"((r)[3]) : "r"(addr))
#define LDSM4T(r, addr)                                                        \
    asm volatile("ldmatrix.sync.aligned.m8n8.x4.trans.shared.b16 {%0,%1,%2,%3}, [%4];" \
        : "=r"((r)[0]), "=r"((r)[1]), "=r"((r)[2]), "=r"((r)[3]) : "r"(addr))

#define CP16(dst, src)                                                         \
    asm volatile("cp.async.cg.shared.global [%0], [%1], 16;" :: "r"(dst), "l"(src))
#define CP_COMMIT() asm volatile("cp.async.commit_group;" ::: "memory")
#define CP_WAIT(n)  asm volatile("cp.async.wait_group %0;" :: "n"(n) : "memory")

#define NINF2  0xFC00FC00u     // f16x2 {-inf, -inf}
#define NINF_H 0xFC000000u     // -inf in high half

// ---------------------------------------------------------------------------
// fp32 -> fp16 conversion, 7 tensors in one launch, 16B stores (R13-proven)
// ---------------------------------------------------------------------------
struct Cvt7 { const float* s[7]; __half* d[7]; int n8[7]; };

__global__ __launch_bounds__(256)
void convert_k(Cvt7 c) {
    const int y = blockIdx.y;
    const float4* s = (const float4*)c.s[y];
    uint4* d = (uint4*)c.d[y];
    const int n8 = c.n8[y];
    for (int i = blockIdx.x * 256 + threadIdx.x; i < n8; i += gridDim.x * 256) {
        float4 v0 = s[2 * i], v1 = s[2 * i + 1];
        d[i] = make_uint4(pkh2(v0.x, v0.y), pkh2(v0.z, v0.w),
                          pkh2(v1.x, v1.y), pkh2(v1.z, v1.w));
    }
}

// ---------------------------------------------------------------------------
// GEMM (R13-proven): Y[M,N] = (X[M,K] @ W[N,K]^T + bias) * osc
// CTA 128x128, 8 warps 2(M)x4(N), warp 64x32, k-chunk 64 halves, 3-stage
// cp.async pipeline (one barrier per 64-k). GS=36 (32 data + 4 pad words).
// ---------------------------------------------------------------------------
#define GS   36
#define GBUF (128 * GS)
#define GEMM_SMEM (3 * 2 * GBUF * 4)    // 110592 B

__device__ __forceinline__ void stY(float* Y, size_t off, float v0, float v1) {
    *(float2*)(Y + off) = make_float2(v0, v1);
}
__device__ __forceinline__ void stY(__half* Y, size_t off, float v0, float v1) {
    *(uint32_t*)(Y + off) = pkh2(v0, v1);
}

template<typename YT>
__device__ __forceinline__ void gemm_body(
    const __half* __restrict__ X, const __half* __restrict__ W,
    const float* __restrict__ bias, YT* __restrict__ Y, int m0, int n0,
    float osc)
{
    extern __shared__ uint32_t dsm[];
    const uint32_t sbase = smem_u32(dsm);
    const int tid = threadIdx.x, lane = tid & 31, wid = tid >> 5;
    const int g = lane >> 2, tg = lane & 3;
    const int wm = (wid & 1) * 64, wn = (wid >> 1) * 32;

    const __half* Xb = X + (size_t)m0 * DMODEL;
    const __half* Wb = W + (size_t)n0 * DMODEL;
    const int r0 = tid >> 3, c0 = tid & 7;   // row 0..31, 16B chunk 0..7

    float acc[4][4][4] = {};

#define G_ISSUE(kt, s) do {                                                    \
        uint32_t ab = sbase + (s) * 2 * GBUF * 4;                              \
        uint32_t bb = ab + GBUF * 4;                                           \
        _Pragma("unroll")                                                      \
        for (int j = 0; j < 4; j++) {                                          \
            const int r = r0 + j * 32;                                         \
            const uint32_t off = (uint32_t)(r * GS + c0 * 4) << 2;             \
            CP16(ab + off, Xb + (size_t)r * DMODEL + (kt) * 64 + c0 * 8);      \
            CP16(bb + off, Wb + (size_t)r * DMODEL + (kt) * 64 + c0 * 8);      \
        } } while (0)

    G_ISSUE(0, 0); CP_COMMIT();
    G_ISSUE(1, 1); CP_COMMIT();

    const uint32_t aF = (uint32_t)((wm + (lane & 15)) * GS + (lane >> 4) * 4) << 2;
    const uint32_t bF = (uint32_t)((wn + (lane >> 4) * 8 + (lane & 7)) * GS
                                   + ((lane >> 3) & 1) * 4) << 2;

    const int NK = DMODEL / 64;   // 12
    for (int kt = 0; kt < NK; kt++) {
        CP_WAIT(1);
        __syncthreads();
        if (kt + 2 < NK) { G_ISSUE(kt + 2, (kt + 2) % 3); }
        CP_COMMIT();

        const uint32_t sb2 = sbase + (kt % 3) * 2 * GBUF * 4;
        const uint32_t ao = sb2 + aF;
        const uint32_t bo = sb2 + GBUF * 4 + bF;
#pragma unroll
        for (int k16 = 0; k16 < 4; k16++) {
            uint32_t a4[4][4], b4[2][4];
#pragma unroll
            for (int mt = 0; mt < 4; mt++)
                LDSM4(a4[mt], ao + (uint32_t)((mt * 16 * GS + k16 * 8) << 2));
#pragma unroll
            for (int np = 0; np < 2; np++)
                LDSM4(b4[np], bo + (uint32_t)((np * 16 * GS + k16 * 8) << 2));
#pragma unroll
            for (int mt = 0; mt < 4; mt++)
#pragma unroll
                for (int nt = 0; nt < 4; nt++)
                    MMA_F16(acc[mt][nt], a4[mt],
                            b4[nt >> 1][(nt & 1) * 2], b4[nt >> 1][(nt & 1) * 2 + 1]);
        }
    }
#undef G_ISSUE

#pragma unroll
    for (int mt = 0; mt < 4; mt++) {
        const int row = m0 + wm + mt * 16 + g;
#pragma unroll
        for (int nt = 0; nt < 4; nt++) {
            const int col = n0 + wn + nt * 8 + 2 * tg;
            const float b0v = bias[col], b1v = bias[col + 1];
            stY(Y, (size_t)row * DMODEL + col,
                (acc[mt][nt][0] + b0v) * osc, (acc[mt][nt][1] + b1v) * osc);
            stY(Y, (size_t)(row + 8) * DMODEL + col,
                (acc[mt][nt][2] + b0v) * osc, (acc[mt][nt][3] + b1v) * osc);
        }
    }
}

#define QS2 (0.125f * 1.44269504f)   // 1/sqrt(64) * log2(e)

__global__ __launch_bounds__(256)
void gemm_qkv(const __half* __restrict__ X0, const __half* __restrict__ X1,
              const __half* __restrict__ X2,
              const __half* __restrict__ W0, const float* __restrict__ b0p,
              const __half* __restrict__ W1, const float* __restrict__ b1p,
              const __half* __restrict__ W2, const float* __restrict__ b2p,
              __half* __restrict__ Q, __half* __restrict__ K, __half* __restrict__ V)
{
    const int m0 = blockIdx.y * 128, n0 = blockIdx.x * 128;
    if (blockIdx.z == 0)      gemm_body(X0, W0, b0p, Q, m0, n0, QS2);  // fold softmax scale
    else if (blockIdx.z == 1) gemm_body(X1, W1, b1p, K, m0, n0, 1.f);
    else                      gemm_body(X2, W2, b2p, V, m0, n0, 1.f);
}

__global__ __launch_bounds__(256)
void gemm_out(const __half* __restrict__ X, const __half* __restrict__ W,
              const float* __restrict__ bias, float* __restrict__ Y)
{
    gemm_body(X, W, bias, Y, blockIdx.y * 128, blockIdx.x * 128, 1.f);
}

// ---------------------------------------------------------------------------
// fp16 flash attention, unnormalized softmax. NEW: S accumulated in fp16
// (m16n8k16 f16-acc = 2x tensor rate); accumulator regs {c01,c23} ARE the
// P A-fragments after h2ex2 — zero packing. Masking in packed f16 (-inf).
// CTA = 128 q rows, 8 warps x 16. 128-row K-tiles, 3-stage cp.async.
// ---------------------------------------------------------------------------
#define ASH  36
#define ABUF (128 * ASH)
#define ATTN_SMEM (3 * 2 * ABUF * 4)     // 110592 B
#define ONES_H2 0x3C003C00u

__global__ __launch_bounds__(256, 2)
void attn_mma(const __half* __restrict__ Q, const __half* __restrict__ K,
              const __half* __restrict__ V, __half* __restrict__ O)
{
    extern __shared__ uint32_t dsm[];
    const uint32_t sbase = smem_u32(dsm);

    const int tid = threadIdx.x, wid = tid >> 5, lane = tid & 31;
    const int g = lane >> 2, tg = lane & 3;
    const int bh = blockIdx.y, b = bh / NHEAD, h = bh % NHEAD;
    const int q0 = ((int)gridDim.x - 1 - (int)blockIdx.x) * 128;  // heavy first
    const int wslab = wid * 16;

    const __half* Qg = Q + (size_t)b * SEQ * DMODEL + h * HSZ;
    const __half* Kg = K + (size_t)b * SEQ * DMODEL + h * HSZ;
    const __half* Vg = V + (size_t)b * SEQ * DMODEL + h * HSZ;

    const int row0 = q0 + wslab + g;
    const int row1 = row0 + 8;

    // Q fragments (already scaled by qs2 in the Q projection epilogue)
    uint32_t qh[4][4];
    {
        const __half* Qr0 = Qg + (size_t)row0 * DMODEL;
        const __half* Qr1 = Qg + (size_t)row1 * DMODEL;
#pragma unroll
        for (int j = 0; j < 4; j++) {
            const int c = j * 16 + 2 * tg;
            qh[j][0] = *(const uint32_t*)(Qr0 + c);
            qh[j][1] = *(const uint32_t*)(Qr1 + c);
            qh[j][2] = *(const uint32_t*)(Qr0 + c + 8);
            qh[j][3] = *(const uint32_t*)(Qr1 + c + 8);
        }
    }

    const int ar0 = tid >> 3, ac0 = tid & 7;   // 16B-chunk mapping

#define A_ISSUE(kt, s) do {                                                    \
        uint32_t kb = sbase + (s) * 2 * ABUF * 4;                              \
        uint32_t vb = kb + ABUF * 4;                                           \
        _Pragma("unroll")                                                      \
        for (int j = 0; j < 4; j++) {                                          \
            const int r = ar0 + j * 32;                                        \
            const uint32_t off = (uint32_t)(r * ASH + ac0 * 4) << 2;           \
            CP16(kb + off, Kg + (size_t)((kt) + r) * DMODEL + ac0 * 8);        \
            CP16(vb + off, Vg + (size_t)((kt) + r) * DMODEL + ac0 * 8);        \
        } } while (0)

    const uint32_t kF = (uint32_t)(((lane >> 4) * 8 + (lane & 7)) * ASH
                                   + ((lane >> 3) & 1) * 4) << 2;
    const uint32_t vF = (uint32_t)((((lane >> 3) & 1) * 8 + (lane & 7)) * ASH
                                   + (lane >> 4) * 4) << 2;

    float o[8][4] = {};
    float ol[4] = {};                         // ones-column: row sums l

    const int nt128 = q0 / 128 + 1;           // causal end = q0 + 128 rows
    A_ISSUE(0, 0); CP_COMMIT();
    if (nt128 > 1) A_ISSUE(128, 1);
    CP_COMMIT();

    for (int t = 0; t < nt128; t++) {
        const int kt = t * 128;
        CP_WAIT(1);
        __syncthreads();
        if (t + 2 < nt128) A_ISSUE((t + 2) * 128, (t + 2) % 3);
        CP_COMMIT();

        const uint32_t sb2 = sbase + (t % 3) * 2 * ABUF * 4;

#pragma unroll
        for (int hh = 0; hh < 2; hh++) {
            const int kb0 = kt + hh * 64;              // first key of this half
            if (kb0 >= q0 + wslab + 16) break;         // beyond this warp's diag

            const uint32_t hoff = (uint32_t)(hh * 64 * ASH) << 2;
            const uint32_t ko = sb2 + hoff + kF;
            const uint32_t vo = sb2 + ABUF * 4 + hoff + vF;

            // S = (qs2*Q) @ K^T in fp16 accumulators
            uint32_t s01[8] = {}, s23[8] = {};
#pragma unroll
            for (int j = 0; j < 4; j++) {
                uint32_t kb4[4][4];
#pragma unroll
                for (int np = 0; np < 4; np++)
                    LDSM4(kb4[np], ko + (uint32_t)((np * 16 * ASH + j * 8) << 2));
#pragma unroll
                for (int nt = 0; nt < 8; nt++)
                    MMA_F16H(s01[nt], s23[nt], qh[j],
                             kb4[nt >> 1][(nt & 1) * 2], kb4[nt >> 1][(nt & 1) * 2 + 1]);
            }

            if (kb0 + 64 > q0 + wslab) {   // diagonal half: packed f16 masking
#pragma unroll
                for (int nt = 0; nt < 8; nt++) {
                    const int cl = kb0 + nt * 8 + 2 * tg;
                    if (cl > row0)          s01[nt] = NINF2;
                    else if (cl + 1 > row0) s01[nt] = (s01[nt] & 0x0000FFFFu) | NINF_H;
                    if (cl > row1)          s23[nt] = NINF2;
                    else if (cl + 1 > row1) s23[nt] = (s23[nt] & 0x0000FFFFu) | NINF_H;
                }
            }

            // P = ex2(S) directly from the f16 accumulators; O += P@V; l += P@1
#pragma unroll
            for (int j = 0; j < 4; j++) {
                uint32_t pa[4];
                pa[0] = h2ex2(s01[2*j]);
                pa[1] = h2ex2(s23[2*j]);
                pa[2] = h2ex2(s01[2*j+1]);
                pa[3] = h2ex2(s23[2*j+1]);
                MMA_F16(ol, pa, ONES_H2, ONES_H2);   // row sums
#pragma unroll
                for (int dtp = 0; dtp < 4; dtp++) {
                    uint32_t vb4[4];
                    LDSM4T(vb4, vo + (uint32_t)((j * 16 * ASH + dtp * 8) << 2));
                    MMA_F16(o[2*dtp    ], pa, vb4[0], vb4[1]);
                    MMA_F16(o[2*dtp + 1], pa, vb4[2], vb4[3]);
                }
            }
        }
    }
#undef A_ISSUE

    const float i0 = 1.f / ol[0], i1 = 1.f / ol[2];
    __half* Op = O + (size_t)b * SEQ * DMODEL + h * HSZ;
#pragma unroll
    for (int dt = 0; dt < 8; dt++) {
        const int col = dt * 8 + 2 * tg;
        *(uint32_t*)(Op + (size_t)row0 * DMODEL + col) = pkh2(o[dt][0] * i0, o[dt][1] * i0);
        *(uint32_t*)(Op + (size_t)row1 * DMODEL + col) = pkh2(o[dt][2] * i1, o[dt][3] * i1);
    }
}

// ---------------------------------------------------------------------------
extern "C" void kernel_launch(void* const* d_in, const int* in_sizes, int n_in,
                              void* d_out, int out_size)
{
    const float* queries = (const float*)d_in[0];
    const float* keys    = (const float*)d_in[1];
    const float* values  = (const float*)d_in[2];
    const float* W_Q = (const float*)d_in[3];
    const float* b_Q = (const float*)d_in[4];
    const float* W_K = (const float*)d_in[5];
    const float* b_K = (const float*)d_in[6];
    const float* W_V = (const float*)d_in[7];
    const float* b_V = (const float*)d_in[8];
    const float* W_O = (const float*)d_in[9];
    const float* b_O = (const float*)d_in[10];
    float* out = (float*)d_out;

    __half *hX, *hW, *pQ, *pK, *pV, *pC;
    cudaGetSymbolAddress((void**)&hX, g_hX);
    cudaGetSymbolAddress((void**)&hW, g_hW);
    cudaGetSymbolAddress((void**)&pQ, g_Q);
    cudaGetSymbolAddress((void**)&pK, g_K);
    cudaGetSymbolAddress((void**)&pV, g_V);
    cudaGetSymbolAddress((void**)&pC, g_Ctx);

    __half* hXq = hX;
    __half* hXk = hX + (size_t)MROWS * DMODEL;
    __half* hXv = hX + 2 * (size_t)MROWS * DMODEL;
    __half* hWQ = hW;
    __half* hWK = hW + (size_t)DMODEL * DMODEL;
    __half* hWV = hW + 2 * (size_t)DMODEL * DMODEL;
    __half* hWO = hW + 3 * (size_t)DMODEL * DMODEL;

    Cvt7 c;
    c.s[0] = queries; c.d[0] = hXq; c.n8[0] = MROWS * DMODEL / 8;
    c.s[1] = keys;    c.d[1] = hXk; c.n8[1] = MROWS * DMODEL / 8;
    c.s[2] = values;  c.d[2] = hXv; c.n8[2] = MROWS * DMODEL / 8;
    c.s[3] = W_Q;     c.d[3] = hWQ; c.n8[3] = DMODEL * DMODEL / 8;
    c.s[4] = W_K;     c.d[4] = hWK; c.n8[4] = DMODEL * DMODEL / 8;
    c.s[5] = W_V;     c.d[5] = hWV; c.n8[5] = DMODEL * DMODEL / 8;
    c.s[6] = W_O;     c.d[6] = hWO; c.n8[6] = DMODEL * DMODEL / 8;
    dim3 gc(1024, 7);
    convert_k<<<gc, 256>>>(c);

    cudaFuncSetAttribute(gemm_qkv, cudaFuncAttributeMaxDynamicSharedMemorySize, GEMM_SMEM);
    cudaFuncSetAttribute(gemm_out, cudaFuncAttributeMaxDynamicSharedMemorySize, GEMM_SMEM);
    cudaFuncSetAttribute(attn_mma, cudaFuncAttributeMaxDynamicSharedMemorySize, ATTN_SMEM);

    dim3 g3(DMODEL / 128, MROWS / 128, 3);   // (6, 64, 3)
    gemm_qkv<<<g3, 256, GEMM_SMEM>>>(hXq, hXk, hXv,
                                     hWQ, b_Q, hWK, b_K, hWV, b_V, pQ, pK, pV);

    dim3 ga(SEQ / 128, BATCH * NHEAD);       // (16, 48)
    attn_mma<<<ga, 256, ATTN_SMEM>>>(pQ, pK, pV, pC);

    dim3 gg(DMODEL / 128, MROWS / 128);      // (6, 64)
    gemm_out<<<gg, 256, GEMM_SMEM>>>(pC, hWO, b_O, out);
}

// round 17
// speedup vs baseline: 1.1230x; 1.0415x over previous
#include <cuda_runtime.h>
#include <cuda_fp16.h>
#include <cstdint>

#define BATCH  4
#define SEQ    2048
#define DMODEL 768
#define NHEAD  12
#define HSZ    64
#define MROWS  (BATCH*SEQ)

// Scratch (alloc-free rule). Half precision everywhere.
__device__ __half g_hX[3][MROWS*DMODEL];     // converted queries/keys/values
__device__ __half g_hW[4][DMODEL*DMODEL];    // converted W_Q/W_K/W_V/W_O
__device__ __half g_Q  [MROWS*DMODEL];
__device__ __half g_K  [MROWS*DMODEL];
__device__ __half g_V  [MROWS*DMODEL];
__device__ __half g_Ctx[MROWS*DMODEL];

__device__ __forceinline__ uint32_t pkh2(float lo, float hi) {
    uint32_t d;
    asm("cvt.rn.f16x2.f32 %0, %1, %2;" : "=r"(d) : "f"(hi), "f"(lo));
    return d;
}
__device__ __forceinline__ uint32_t h2ex2(uint32_t x) {
    uint32_t d; asm("ex2.approx.f16x2 %0, %1;" : "=r"(d) : "r"(x)); return d;
}
__device__ __forceinline__ uint32_t smem_u32(const void* p) {
    uint32_t a;
    asm("{ .reg .u64 t; cvta.to.shared.u64 t, %1; cvt.u32.u64 %0, t; }"
        : "=r"(a) : "l"(p));
    return a;
}

#define MMA_F16(d, a, b0v, b1v)                                                \
    asm volatile("mma.sync.aligned.m16n8k16.row.col.f32.f16.f16.f32 "          \
        "{%0,%1,%2,%3}, {%4,%5,%6,%7}, {%8,%9}, {%0,%1,%2,%3};"                \
        : "+f"((d)[0]), "+f"((d)[1]), "+f"((d)[2]), "+f"((d)[3])               \
        : "r"((a)[0]), "r"((a)[1]), "r"((a)[2]), "r"((a)[3]),                  \
          "r"(b0v), "r"(b1v))

#define LDSM4(r, addr)                                                         \
    asm volatile("ldmatrix.sync.aligned.m8n8.x4.shared.b16 {%0,%1,%2,%3}, [%4];" \
        : "=r"((r)[0]), "=r"((r)[1]), "=r"((r)[2]), "=r"((r)[3]) : "r"(addr))
#define LDSM4T(r, addr)                                                        \
    asm volatile("ldmatrix.sync.aligned.m8n8.x4.trans.shared.b16 {%0,%1,%2,%3}, [%4];" \
        : "=r"((r)[0]), "=r"((r)[1]), "=r"((r)[2]), "=r"((r)[3]) : "r"(addr))

#define CP16(dst, src)                                                         \
    asm volatile("cp.async.cg.shared.global [%0], [%1], 16;" :: "r"(dst), "l"(src))
#define CP_COMMIT() asm volatile("cp.async.commit_group;" ::: "memory")
#define CP_WAIT(n)  asm volatile("cp.async.wait_group %0;" :: "n"(n) : "memory")

// ---------------------------------------------------------------------------
// fp32 -> fp16 conversion, 7 tensors in one launch, 16B stores (R13-proven)
// ---------------------------------------------------------------------------
struct Cvt7 { const float* s[7]; __half* d[7]; int n8[7]; };

__global__ __launch_bounds__(256)
void convert_k(Cvt7 c) {
    const int y = blockIdx.y;
    const float4* s = (const float4*)c.s[y];
    uint4* d = (uint4*)c.d[y];
    const int n8 = c.n8[y];
    for (int i = blockIdx.x * 256 + threadIdx.x; i < n8; i += gridDim.x * 256) {
        float4 v0 = s[2 * i], v1 = s[2 * i + 1];
        d[i] = make_uint4(pkh2(v0.x, v0.y), pkh2(v0.z, v0.w),
                          pkh2(v1.x, v1.y), pkh2(v1.z, v1.w));
    }
}

// ---------------------------------------------------------------------------
// GEMM: Y[M,N] = (X[M,K] @ W[N,K]^T + bias) * osc   (half in, fp32 accum)
// NEW config: CTA 128x128, 4 warps 2(M)x2(N), warp tile 64x64, k-chunk 64,
// 2-stage cp.async pipeline, 3 CTAs/SM (12 warps/SM, 2x ILP per warp).
// GS=36 (32 data + 4 pad words), stage = 36864 B, smem = 73728 B/CTA.
// ---------------------------------------------------------------------------
#define GS   36
#define GBUF (128 * GS)
#define GEMM_SMEM (2 * 2 * GBUF * 4)    // 73728 B

__device__ __forceinline__ void stY(float* Y, size_t off, float v0, float v1) {
    *(float2*)(Y + off) = make_float2(v0, v1);
}
__device__ __forceinline__ void stY(__half* Y, size_t off, float v0, float v1) {
    *(uint32_t*)(Y + off) = pkh2(v0, v1);
}

template<typename YT>
__device__ __forceinline__ void gemm_body(
    const __half* __restrict__ X, const __half* __restrict__ W,
    const float* __restrict__ bias, YT* __restrict__ Y, int m0, int n0,
    float osc)
{
    extern __shared__ uint32_t dsm[];
    const uint32_t sbase = smem_u32(dsm);
    const int tid = threadIdx.x, lane = tid & 31, wid = tid >> 5;
    const int g = lane >> 2, tg = lane & 3;
    const int wm = (wid & 1) * 64, wn = (wid >> 1) * 64;

    const __half* Xb = X + (size_t)m0 * DMODEL;
    const __half* Wb = W + (size_t)n0 * DMODEL;
    const int r0 = tid >> 3, c0 = tid & 7;   // row 0..15, 16B chunk 0..7

    float acc[4][8][4] = {};

#define G_ISSUE(kt, s) do {                                                    \
        uint32_t ab = sbase + (s) * 2 * GBUF * 4;                              \
        uint32_t bb = ab + GBUF * 4;                                           \
        _Pragma("unroll")                                                      \
        for (int j = 0; j < 8; j++) {                                          \
            const int r = r0 + j * 16;                                         \
            const uint32_t off = (uint32_t)(r * GS + c0 * 4) << 2;             \
            CP16(ab + off, Xb + (size_t)r * DMODEL + (kt) * 64 + c0 * 8);      \
            CP16(bb + off, Wb + (size_t)r * DMODEL + (kt) * 64 + c0 * 8);      \
        } } while (0)

    G_ISSUE(0, 0); CP_COMMIT();

    const uint32_t aF = (uint32_t)((wm + (lane & 15)) * GS + (lane >> 4) * 4) << 2;
    const uint32_t bF = (uint32_t)((wn + (lane >> 4) * 8 + (lane & 7)) * GS
                                   + ((lane >> 3) & 1) * 4) << 2;

    const int NK = DMODEL / 64;   // 12
    for (int kt = 0; kt < NK; kt++) {
        CP_WAIT(0);
        __syncthreads();
        if (kt + 1 < NK) { G_ISSUE(kt + 1, (kt + 1) & 1); }
        CP_COMMIT();

        const uint32_t sb2 = sbase + (kt & 1) * 2 * GBUF * 4;
        const uint32_t ao = sb2 + aF;
        const uint32_t bo = sb2 + GBUF * 4 + bF;
#pragma unroll
        for (int k16 = 0; k16 < 4; k16++) {
            uint32_t a4[4][4], b4[4][4];
#pragma unroll
            for (int mt = 0; mt < 4; mt++)
                LDSM4(a4[mt], ao + (uint32_t)((mt * 16 * GS + k16 * 8) << 2));
#pragma unroll
            for (int np = 0; np < 4; np++)
                LDSM4(b4[np], bo + (uint32_t)((np * 16 * GS + k16 * 8) << 2));
#pragma unroll
            for (int mt = 0; mt < 4; mt++)
#pragma unroll
                for (int nt = 0; nt < 8; nt++)
                    MMA_F16(acc[mt][nt], a4[mt],
                            b4[nt >> 1][(nt & 1) * 2], b4[nt >> 1][(nt & 1) * 2 + 1]);
        }
    }
#undef G_ISSUE

#pragma unroll
    for (int mt = 0; mt < 4; mt++) {
        const int row = m0 + wm + mt * 16 + g;
#pragma unroll
        for (int nt = 0; nt < 8; nt++) {
            const int col = n0 + wn + nt * 8 + 2 * tg;
            const float b0v = bias[col], b1v = bias[col + 1];
            stY(Y, (size_t)row * DMODEL + col,
                (acc[mt][nt][0] + b0v) * osc, (acc[mt][nt][1] + b1v) * osc);
            stY(Y, (size_t)(row + 8) * DMODEL + col,
                (acc[mt][nt][2] + b0v) * osc, (acc[mt][nt][3] + b1v) * osc);
        }
    }
}

#define QS2 (0.125f * 1.44269504f)   // 1/sqrt(64) * log2(e)

__global__ __launch_bounds__(128, 3)
void gemm_qkv(const __half* __restrict__ X0, const __half* __restrict__ X1,
              const __half* __restrict__ X2,
              const __half* __restrict__ W0, const float* __restrict__ b0p,
              const __half* __restrict__ W1, const float* __restrict__ b1p,
              const __half* __restrict__ W2, const float* __restrict__ b2p,
              __half* __restrict__ Q, __half* __restrict__ K, __half* __restrict__ V)
{
    const int m0 = blockIdx.y * 128, n0 = blockIdx.x * 128;
    if (blockIdx.z == 0)      gemm_body(X0, W0, b0p, Q, m0, n0, QS2);  // fold softmax scale
    else if (blockIdx.z == 1) gemm_body(X1, W1, b1p, K, m0, n0, 1.f);
    else                      gemm_body(X2, W2, b2p, V, m0, n0, 1.f);
}

__global__ __launch_bounds__(128, 3)
void gemm_out(const __half* __restrict__ X, const __half* __restrict__ W,
              const float* __restrict__ bias, float* __restrict__ Y)
{
    gemm_body(X, W, bias, Y, blockIdx.y * 128, blockIdx.x * 128, 1.f);
}

// ---------------------------------------------------------------------------
// fp16 flash attention (R13-proven, unchanged). Unnormalized softmax, fp32 S.
// CTA = 128 q rows, 8 warps x 16. 128-row K-tiles, 3-stage cp.async.
// ---------------------------------------------------------------------------
#define ASH  36
#define ABUF (128 * ASH)
#define ATTN_SMEM (3 * 2 * ABUF * 4)     // 110592 B
#define ONES_H2 0x3C003C00u

__global__ __launch_bounds__(256, 2)
void attn_mma(const __half* __restrict__ Q, const __half* __restrict__ K,
              const __half* __restrict__ V, __half* __restrict__ O)
{
    extern __shared__ uint32_t dsm[];
    const uint32_t sbase = smem_u32(dsm);

    const int tid = threadIdx.x, wid = tid >> 5, lane = tid & 31;
    const int g = lane >> 2, tg = lane & 3;
    const int bh = blockIdx.y, b = bh / NHEAD, h = bh % NHEAD;
    const int q0 = ((int)gridDim.x - 1 - (int)blockIdx.x) * 128;  // heavy first
    const int wslab = wid * 16;

    const __half* Qg = Q + (size_t)b * SEQ * DMODEL + h * HSZ;
    const __half* Kg = K + (size_t)b * SEQ * DMODEL + h * HSZ;
    const __half* Vg = V + (size_t)b * SEQ * DMODEL + h * HSZ;

    const int row0 = q0 + wslab + g;
    const int row1 = row0 + 8;

    uint32_t qh[4][4];
    {
        const __half* Qr0 = Qg + (size_t)row0 * DMODEL;
        const __half* Qr1 = Qg + (size_t)row1 * DMODEL;
#pragma unroll
        for (int j = 0; j < 4; j++) {
            const int c = j * 16 + 2 * tg;
            qh[j][0] = *(const uint32_t*)(Qr0 + c);
            qh[j][1] = *(const uint32_t*)(Qr1 + c);
            qh[j][2] = *(const uint32_t*)(Qr0 + c + 8);
            qh[j][3] = *(const uint32_t*)(Qr1 + c + 8);
        }
    }

    const int ar0 = tid >> 3, ac0 = tid & 7;

#define A_ISSUE(kt, s) do {                                                    \
        uint32_t kb = sbase + (s) * 2 * ABUF * 4;                              \
        uint32_t vb = kb + ABUF * 4;                                           \
        _Pragma("unroll")                                                      \
        for (int j = 0; j < 4; j++) {                                          \
            const int r = ar0 + j * 32;                                        \
            const uint32_t off = (uint32_t)(r * ASH + ac0 * 4) << 2;           \
            CP16(kb + off, Kg + (size_t)((kt) + r) * DMODEL + ac0 * 8);        \
            CP16(vb + off, Vg + (size_t)((kt) + r) * DMODEL + ac0 * 8);        \
        } } while (0)

    const uint32_t kF = (uint32_t)(((lane >> 4) * 8 + (lane & 7)) * ASH
                                   + ((lane >> 3) & 1) * 4) << 2;
    const uint32_t vF = (uint32_t)((((lane >> 3) & 1) * 8 + (lane & 7)) * ASH
                                   + (lane >> 4) * 4) << 2;

    float o[8][4] = {};
    float ol[4] = {};

    const int nt128 = q0 / 128 + 1;
    A_ISSUE(0, 0); CP_COMMIT();
    if (nt128 > 1) A_ISSUE(128, 1);
    CP_COMMIT();

    for (int t = 0; t < nt128; t++) {
        const int kt = t * 128;
        CP_WAIT(1);
        __syncthreads();
        if (t + 2 < nt128) A_ISSUE((t + 2) * 128, (t + 2) % 3);
        CP_COMMIT();

        const uint32_t sb2 = sbase + (t % 3) * 2 * ABUF * 4;

#pragma unroll
        for (int hh = 0; hh < 2; hh++) {
            const int kb0 = kt + hh * 64;
            if (kb0 >= q0 + wslab + 16) break;

            const uint32_t hoff = (uint32_t)(hh * 64 * ASH) << 2;
            const uint32_t ko = sb2 + hoff + kF;
            const uint32_t vo = sb2 + ABUF * 4 + hoff + vF;

            float s[8][4] = {};
#pragma unroll
            for (int j = 0; j < 4; j++) {
                uint32_t kb4[4][4];
#pragma unroll
                for (int np = 0; np < 4; np++)
                    LDSM4(kb4[np], ko + (uint32_t)((np * 16 * ASH + j * 8) << 2));
#pragma unroll
                for (int nt = 0; nt < 8; nt++)
                    MMA_F16(s[nt], qh[j],
                            kb4[nt >> 1][(nt & 1) * 2], kb4[nt >> 1][(nt & 1) * 2 + 1]);
            }

            if (kb0 + 64 > q0 + wslab) {
#pragma unroll
                for (int nt = 0; nt < 8; nt++) {
                    const int cl = kb0 + nt * 8 + 2 * tg;
                    if (cl     > row0) s[nt][0] = -1e30f;
                    if (cl + 1 > row0) s[nt][1] = -1e30f;
                    if (cl     > row1) s[nt][2] = -1e30f;
                    if (cl + 1 > row1) s[nt][3] = -1e30f;
                }
            }

#pragma unroll
            for (int j = 0; j < 4; j++) {
                uint32_t pa[4];
                pa[0] = h2ex2(pkh2(s[2*j  ][0], s[2*j  ][1]));
                pa[1] = h2ex2(pkh2(s[2*j  ][2], s[2*j  ][3]));
                pa[2] = h2ex2(pkh2(s[2*j+1][0], s[2*j+1][1]));
                pa[3] = h2ex2(pkh2(s[2*j+1][2], s[2*j+1][3]));
                MMA_F16(ol, pa, ONES_H2, ONES_H2);
#pragma unroll
                for (int dtp = 0; dtp < 4; dtp++) {
                    uint32_t vb4[4];
                    LDSM4T(vb4, vo + (uint32_t)((j * 16 * ASH + dtp * 8) << 2));
                    MMA_F16(o[2*dtp    ], pa, vb4[0], vb4[1]);
                    MMA_F16(o[2*dtp + 1], pa, vb4[2], vb4[3]);
                }
            }
        }
    }
#undef A_ISSUE

    const float i0 = 1.f / ol[0], i1 = 1.f / ol[2];
    __half* Op = O + (size_t)b * SEQ * DMODEL + h * HSZ;
#pragma unroll
    for (int dt = 0; dt < 8; dt++) {
        const int col = dt * 8 + 2 * tg;
        *(uint32_t*)(Op + (size_t)row0 * DMODEL + col) = pkh2(o[dt][0] * i0, o[dt][1] * i0);
        *(uint32_t*)(Op + (size_t)row1 * DMODEL + col) = pkh2(o[dt][2] * i1, o[dt][3] * i1);
    }
}

// ---------------------------------------------------------------------------
extern "C" void kernel_launch(void* const* d_in, const int* in_sizes, int n_in,
                              void* d_out, int out_size)
{
    const float* queries = (const float*)d_in[0];
    const float* keys    = (const float*)d_in[1];
    const float* values  = (const float*)d_in[2];
    const float* W_Q = (const float*)d_in[3];
    const float* b_Q = (const float*)d_in[4];
    const float* W_K = (const float*)d_in[5];
    const float* b_K = (const float*)d_in[6];
    const float* W_V = (const float*)d_in[7];
    const float* b_V = (const float*)d_in[8];
    const float* W_O = (const float*)d_in[9];
    const float* b_O = (const float*)d_in[10];
    float* out = (float*)d_out;

    __half *hX, *hW, *pQ, *pK, *pV, *pC;
    cudaGetSymbolAddress((void**)&hX, g_hX);
    cudaGetSymbolAddress((void**)&hW, g_hW);
    cudaGetSymbolAddress((void**)&pQ, g_Q);
    cudaGetSymbolAddress((void**)&pK, g_K);
    cudaGetSymbolAddress((void**)&pV, g_V);
    cudaGetSymbolAddress((void**)&pC, g_Ctx);

    __half* hXq = hX;
    __half* hXk = hX + (size_t)MROWS * DMODEL;
    __half* hXv = hX + 2 * (size_t)MROWS * DMODEL;
    __half* hWQ = hW;
    __half* hWK = hW + (size_t)DMODEL * DMODEL;
    __half* hWV = hW + 2 * (size_t)DMODEL * DMODEL;
    __half* hWO = hW + 3 * (size_t)DMODEL * DMODEL;

    Cvt7 c;
    c.s[0] = queries; c.d[0] = hXq; c.n8[0] = MROWS * DMODEL / 8;
    c.s[1] = keys;    c.d[1] = hXk; c.n8[1] = MROWS * DMODEL / 8;
    c.s[2] = values;  c.d[2] = hXv; c.n8[2] = MROWS * DMODEL / 8;
    c.s[3] = W_Q;     c.d[3] = hWQ; c.n8[3] = DMODEL * DMODEL / 8;
    c.s[4] = W_K;     c.d[4] = hWK; c.n8[4] = DMODEL * DMODEL / 8;
    c.s[5] = W_V;     c.d[5] = hWV; c.n8[5] = DMODEL * DMODEL / 8;
    c.s[6] = W_O;     c.d[6] = hWO; c.n8[6] = DMODEL * DMODEL / 8;
    dim3 gc(1024, 7);
    convert_k<<<gc, 256>>>(c);

    cudaFuncSetAttribute(gemm_qkv, cudaFuncAttributeMaxDynamicSharedMemorySize, GEMM_SMEM);
    cudaFuncSetAttribute(gemm_out, cudaFuncAttributeMaxDynamicSharedMemorySize, GEMM_SMEM);
    cudaFuncSetAttribute(attn_mma, cudaFuncAttributeMaxDynamicSharedMemorySize, ATTN_SMEM);

    dim3 g3(DMODEL / 128, MROWS / 128, 3);   // (6, 64, 3)
    gemm_qkv<<<g3, 128, GEMM_SMEM>>>(hXq, hXk, hXv,
                                     hWQ, b_Q, hWK, b_K, hWV, b_V, pQ, pK, pV);

    dim3 ga(SEQ / 128, BATCH * NHEAD);       // (16, 48)
    attn_mma<<<ga, 256, ATTN_SMEM>>>(pQ, pK, pV, pC);

    dim3 gg(DMODEL / 128, MROWS / 128);      // (6, 64)
    gemm_out<<<gg, 128, GEMM_SMEM>>>(pC, hWO, b_O, out);
}